// round 16
// baseline (speedup 1.0000x reference)
#include <cuda_runtime.h>
#include <cuda_fp16.h>
#include <cstdint>

// ===========================================================================
// VQ-VAE quantizer — fp16 2-split mma.sync m16n8k16 argmin-GEMM (round 16).
//   x [4,64,32,32,32] fp32, weight [512,64] fp32
// out: quantized_st (8.4M), embed_idx (131072 as float), latent_loss (1)
//
// score_j = wsq_j - 2*dot(x,w_j); dot = Ahi*Bhi + Ahi*Blo + Alo*Bhi (fp16
// 2-split, fp32 acc). Round 16 = round 15 with the 12-deep MMA chain split
// into TWO accumulators (depth 8 + 4) -> 4 indep chains/warp with unroll 2,
// at +4 regs (still 3 blocks/SM, 6 warps/SMSP). x-load vectorized LDG.128.
// ===========================================================================

static constexpr int C = 64, E = 512, S = 32768;

__device__ float    g_partials[1024];
__device__ float    g_wsq[E];
__device__ uint4    g_bfrag[8192];   // (nt*4+ks)*32+lane : {hi0,hi1,lo0,lo1}
__device__ unsigned g_count = 0;

#define MMA_F16(acc, a, b0, b1) \
    asm volatile("mma.sync.aligned.m16n8k16.row.col.f32.f16.f16.f32 " \
                 "{%0,%1,%2,%3}, {%4,%5,%6,%7}, {%8,%9}, {%0,%1,%2,%3};" \
                 : "+f"((acc)[0]), "+f"((acc)[1]), "+f"((acc)[2]), "+f"((acc)[3]) \
                 : "r"((a)[0]), "r"((a)[1]), "r"((a)[2]), "r"((a)[3]), \
                   "r"(b0), "r"(b1))

__device__ __forceinline__ void split_pack(float v0, float v1,
                                           uint32_t& hi, uint32_t& lo)
{
    const __half h0 = __float2half_rn(v0);
    const __half h1 = __float2half_rn(v1);
    const float  r0 = v0 - __half2float(h0);
    const float  r1 = v1 - __half2float(h1);
    const __half g0 = __float2half_rn(r0);
    const __half g1 = __float2half_rn(r1);
    hi = (uint32_t)__half_as_ushort(h0) | ((uint32_t)__half_as_ushort(h1) << 16);
    lo = (uint32_t)__half_as_ushort(g0) | ((uint32_t)__half_as_ushort(g1) << 16);
}

// ---- smem layout (float offsets), per block ----
static constexpr int OFF_XS  = 0;                   // [128][65] = 8320
static constexpr int OFF_B   = 8320;                // 1024 uint4 = 4096 floats
static constexpr int OFF_WSQ = OFF_B + 4096;        // [512]
static constexpr int OFF_IDX = OFF_WSQ + 512;       // [128] int
static constexpr int OFF_RED = OFF_IDX + 128;       // [256]
static constexpr int SMEM_FLOATS = OFF_RED + 256;   // 13312 -> 53248 B

// ---------------------------------------------------------------------------
// Prep: split codebook into B-fragment layout + wsq. 64 blocks x 128 thr.
// ---------------------------------------------------------------------------
__global__ void __launch_bounds__(128) prep_kernel(const float* __restrict__ w)
{
    const int sl = blockIdx.x * 128 + threadIdx.x;   // 0..8191
    const int lane = sl & 31;
    const int ks   = (sl >> 5) & 3;
    const int nt   = sl >> 7;
    const int code = nt * 8 + (lane >> 2);
    const int k0   = ks * 16 + ((lane & 3) << 1);
    const float* wr = w + code * C + k0;
    uint32_t h0, g0, h1, g1;
    split_pack(wr[0], wr[1], h0, g0);
    split_pack(wr[8], wr[9], h1, g1);
    g_bfrag[sl] = make_uint4(h0, h1, g0, g1);

    if (sl < E) {
        const float4* r = (const float4*)(w + sl * C);
        float s = 0.f;
        #pragma unroll
        for (int q = 0; q < 16; ++q) {
            const float4 f = r[q];
            s = fmaf(f.x, f.x, s); s = fmaf(f.y, f.y, s);
            s = fmaf(f.z, f.z, s); s = fmaf(f.w, f.w, s);
        }
        g_wsq[sl] = s;
    }
}

// ===========================================================================
__global__ void __launch_bounds__(256, 3) vq_hmma_kernel(
    const float* __restrict__ x, const float* __restrict__ w,
    float* __restrict__ out_q, float* __restrict__ out_idx,
    float* __restrict__ out_loss, float inv_n)
{
    extern __shared__ float smem[];
    float* xs   = smem + OFF_XS;
    uint4* bbuf = (uint4*)(smem + OFF_B);
    float* wsqs = smem + OFF_WSQ;
    int*   idxb = (int*)(smem + OFF_IDX);
    float* redb = smem + OFF_RED;
    __shared__ int is_last;

    const int tid = threadIdx.x;
    const int l   = tid & 31;
    const int wid = tid >> 5;           // 0..7
    const int wp  = wid * 16;           // warp's first position (local)

    const int p0 = blockIdx.x * 128;
    const int b  = p0 >> 15;
    const int s0 = p0 & (S - 1);
    const float* xb = x + (size_t)b * C * S + s0;

    // ---- x tile -> smem [pos][ch], LDG.128 along positions ----
    #pragma unroll
    for (int it = 0; it < 8; ++it) {
        const int e   = it * 256 + tid;      // 2048 float4 total
        const int k   = e >> 5;              // channel
        const int pl4 = (e & 31) << 2;       // position group of 4
        const float4 v = *(const float4*)(xb + (size_t)k * S + pl4);
        xs[(pl4 + 0) * 65 + k] = v.x;
        xs[(pl4 + 1) * 65 + k] = v.y;
        xs[(pl4 + 2) * 65 + k] = v.z;
        xs[(pl4 + 3) * 65 + k] = v.w;
    }
    wsqs[tid]       = g_wsq[tid];
    wsqs[tid + 256] = g_wsq[tid + 256];
    __syncthreads();

    // ---- A fragments (fp16 hi/lo): 1 M-tile, 4 ksteps x 4 regs ----
    uint32_t Ahi[4][4], Alo[4][4];
    {
        const int r0 = wp + (l >> 2);
        const int r1 = r0 + 8;
        #pragma unroll
        for (int ks = 0; ks < 4; ++ks) {
            const int k0 = ks * 16 + ((l & 3) << 1);
            split_pack(xs[r0 * 65 + k0],     xs[r0 * 65 + k0 + 1], Ahi[ks][0], Alo[ks][0]);
            split_pack(xs[r1 * 65 + k0],     xs[r1 * 65 + k0 + 1], Ahi[ks][1], Alo[ks][1]);
            split_pack(xs[r0 * 65 + k0 + 8], xs[r0 * 65 + k0 + 9], Ahi[ks][2], Alo[ks][2]);
            split_pack(xs[r1 * 65 + k0 + 8], xs[r1 * 65 + k0 + 9], Ahi[ks][3], Alo[ks][3]);
        }
    }

    float bv0 = 3.4e38f, bv1 = 3.4e38f;
    int   bj0 = 0,       bj1 = 0;

    // ---- 8 chunks of 64 codes ----
    #pragma unroll 1
    for (int chunk = 0; chunk < 8; ++chunk) {
        const int base = chunk * 64;
        __syncthreads();   // previous chunk's readers done

        // fill B: raw copy from precomputed fragment buffer (L2-resident)
        {
            const uint4* src = g_bfrag + chunk * 1024;
            #pragma unroll
            for (int it = 0; it < 4; ++it)
                bbuf[it * 256 + tid] = src[it * 256 + tid];
        }
        __syncthreads();

        #pragma unroll 2
        for (int nt = 0; nt < 8; ++nt) {
            // two independent accumulator chains (depth 8 + depth 4)
            float ac0[4] = {0.f, 0.f, 0.f, 0.f};
            float ac1[4] = {0.f, 0.f, 0.f, 0.f};
            #pragma unroll
            for (int ks = 0; ks < 4; ++ks) {
                const uint4 bq = bbuf[(nt * 4 + ks) * 32 + l];
                MMA_F16(ac0, Ahi[ks], bq.x, bq.y);   // hi*hi
                MMA_F16(ac1, Ahi[ks], bq.z, bq.w);   // hi*lo
                MMA_F16(ac0, Alo[ks], bq.x, bq.y);   // lo*hi
            }
            const int cb = base + nt * 8 + ((l & 3) << 1);
            const float wq0 = wsqs[cb], wq1 = wsqs[cb + 1];
            const float sc0 = fmaf(-2.f, ac0[0] + ac1[0], wq0);
            const float sc1 = fmaf(-2.f, ac0[1] + ac1[1], wq1);
            const float sc2 = fmaf(-2.f, ac0[2] + ac1[2], wq0);
            const float sc3 = fmaf(-2.f, ac0[3] + ac1[3], wq1);
            {   // row l/4
                const int   jm = (sc1 < sc0) ? cb + 1 : cb;   // tie -> lower j
                const float sm = fminf(sc0, sc1);
                bj0 = (sm < bv0) ? jm : bj0;  bv0 = fminf(bv0, sm);
            }
            {   // row l/4+8
                const int   jm = (sc3 < sc2) ? cb + 1 : cb;
                const float sm = fminf(sc2, sc3);
                bj1 = (sm < bv1) ? jm : bj1;  bv1 = fminf(bv1, sm);
            }
        }
    }

    // ---- cross-lane argmin over quads (cols split across l%4) ----
    #pragma unroll
    for (int off = 1; off <= 2; off <<= 1) {
        float ov; int oj;
        ov = __shfl_xor_sync(0xffffffffu, bv0, off);
        oj = __shfl_xor_sync(0xffffffffu, bj0, off);
        if (ov < bv0 || (ov == bv0 && oj < bj0)) { bv0 = ov; bj0 = oj; }
        ov = __shfl_xor_sync(0xffffffffu, bv1, off);
        oj = __shfl_xor_sync(0xffffffffu, bj1, off);
        if (ov < bv1 || (ov == bv1 && oj < bj1)) { bv1 = ov; bj1 = oj; }
    }
    if ((l & 3) == 0) {
        const int r = l >> 2;
        idxb[wp + r]     = bj0;
        idxb[wp + r + 8] = bj1;
    }
    __syncthreads();

    // ---- epilogue: 2 threads per position, 32 channels each ----
    const int pos = tid & 127;
    const int co  = (tid >> 7) * 32;
    const int j   = idxb[pos];
    if (tid < 128) out_idx[p0 + pos] = (float)j;

    float acc = 0.f;
    const float4* wr = (const float4*)(w + j * C + co);
    float* qb = out_q + (size_t)b * C * S + (size_t)co * S + s0 + pos;
    #pragma unroll
    for (int q4 = 0; q4 < 8; ++q4) {
        const float4 f = wr[q4];
        const float qv[4] = {f.x, f.y, f.z, f.w};
        #pragma unroll
        for (int u = 0; u < 4; ++u) {
            const int c = q4 * 4 + u;
            const float xv = xs[pos * 65 + co + c];
            const float d = qv[u] - xv;
            qb[(size_t)c * S] = d + xv;    // fl(fl(w-x)+x)
            acc = fmaf(d, d, acc);
        }
    }

    redb[tid] = acc;
    __syncthreads();
    #pragma unroll
    for (int off = 128; off > 0; off >>= 1) {
        if (tid < off) redb[tid] += redb[tid + off];
        __syncthreads();
    }

    // ---- fused deterministic loss finalization (last block) ----
    if (tid == 0) {
        g_partials[blockIdx.x] = redb[0];
        __threadfence();
        const unsigned t = atomicAdd(&g_count, 1u);
        is_last = (t == (unsigned)(gridDim.x - 1)) ? 1 : 0;
    }
    __syncthreads();
    if (is_last) {
        __threadfence();   // acquire: all partials visible
        float a = g_partials[tid] + g_partials[tid + 256] +
                  g_partials[tid + 512] + g_partials[tid + 768];
        redb[tid] = a;
        __syncthreads();
        #pragma unroll
        for (int off = 128; off > 0; off >>= 1) {
            if (tid < off) redb[tid] += redb[tid + off];
            __syncthreads();
        }
        if (tid == 0) {
            out_loss[0] = 0.25f * redb[0] * inv_n;
            g_count = 0;   // reset for next graph replay
        }
    }
}

// ---------------------------------------------------------------------------
extern "C" void kernel_launch(void* const* d_in, const int* in_sizes, int n_in,
                              void* d_out, int out_size)
{
    const float* x = (const float*)d_in[0];
    const float* w = (const float*)d_in[1];
    float* out = (float*)d_out;

    const int n_x  = in_sizes[0];   // 8388608
    const int npos = n_x / C;       // 131072

    float* out_q    = out;
    float* out_idx  = out + n_x;
    float* out_loss = out + n_x + npos;

    const int smem_bytes = SMEM_FLOATS * (int)sizeof(float);  // 53248
    cudaFuncSetAttribute(vq_hmma_kernel,
                         cudaFuncAttributeMaxDynamicSharedMemorySize, smem_bytes);

    prep_kernel<<<64, 128>>>(w);
    const int blocks = npos / 128;   // 1024
    vq_hmma_kernel<<<blocks, 256, smem_bytes>>>(x, w, out_q, out_idx,
                                                out_loss, 1.0f / (float)n_x);
}

// round 17
// speedup vs baseline: 1.0751x; 1.0751x over previous
#include <cuda_runtime.h>
#include <cuda_fp16.h>
#include <cstdint>

// ===========================================================================
// VQ-VAE quantizer — fp16 2-split mma.sync m16n8k16 argmin-GEMM (round 17).
//   x [4,64,32,32,32] fp32, weight [512,64] fp32
// out: quantized_st (8.4M), embed_idx (131072 as float), latent_loss (1)
//
// score_j = wsq_j - 2*dot(x,w_j); dot = Ahi*Bhi + Ahi*Blo + Alo*Bhi (fp16
// 2-split, fp32 acc, chained). Round 17: kernel was smem-BW bound
// (L1 66.7% vs tensor 50.5%). 2 M-tiles/warp doubles B reuse (1 LDS.128 ->
// 6 MMAs); 128-thr blocks x 5 blocks/SM keeps 5 warps/SMSP at 102 regs.
// 16 B-chunks of 32 codes (8KB) so 5 x 44.5KB smem fits.
// ===========================================================================

static constexpr int C = 64, E = 512, S = 32768;

__device__ float    g_partials[1024];
__device__ float    g_wsq[E];
__device__ uint4    g_bfrag[8192];   // (nt*4+ks)*32+lane : {hi0,hi1,lo0,lo1}
__device__ unsigned g_count = 0;

#define MMA_F16(acc, a, b0, b1) \
    asm volatile("mma.sync.aligned.m16n8k16.row.col.f32.f16.f16.f32 " \
                 "{%0,%1,%2,%3}, {%4,%5,%6,%7}, {%8,%9}, {%0,%1,%2,%3};" \
                 : "+f"((acc)[0]), "+f"((acc)[1]), "+f"((acc)[2]), "+f"((acc)[3]) \
                 : "r"((a)[0]), "r"((a)[1]), "r"((a)[2]), "r"((a)[3]), \
                   "r"(b0), "r"(b1))

__device__ __forceinline__ void split_pack(float v0, float v1,
                                           uint32_t& hi, uint32_t& lo)
{
    const __half h0 = __float2half_rn(v0);
    const __half h1 = __float2half_rn(v1);
    const float  r0 = v0 - __half2float(h0);
    const float  r1 = v1 - __half2float(h1);
    const __half g0 = __float2half_rn(r0);
    const __half g1 = __float2half_rn(r1);
    hi = (uint32_t)__half_as_ushort(h0) | ((uint32_t)__half_as_ushort(h1) << 16);
    lo = (uint32_t)__half_as_ushort(g0) | ((uint32_t)__half_as_ushort(g1) << 16);
}

// ---- smem layout (float offsets), per block ----
static constexpr int OFF_XS  = 0;                   // [128][65] = 8320
static constexpr int OFF_B   = 8320;                // 512 uint4 = 2048 floats
static constexpr int OFF_WSQ = OFF_B + 2048;        // [512]
static constexpr int OFF_IDX = OFF_WSQ + 512;       // [128] int
static constexpr int OFF_RED = OFF_IDX + 128;       // [128]
static constexpr int SMEM_FLOATS = OFF_RED + 128;   // 11136 -> 44544 B

// ---------------------------------------------------------------------------
// Prep: split codebook into B-fragment layout + wsq. 64 blocks x 128 thr.
// ---------------------------------------------------------------------------
__global__ void __launch_bounds__(128) prep_kernel(const float* __restrict__ w)
{
    const int sl = blockIdx.x * 128 + threadIdx.x;   // 0..8191
    const int lane = sl & 31;
    const int ks   = (sl >> 5) & 3;
    const int nt   = sl >> 7;
    const int code = nt * 8 + (lane >> 2);
    const int k0   = ks * 16 + ((lane & 3) << 1);
    const float* wr = w + code * C + k0;
    uint32_t h0, g0, h1, g1;
    split_pack(wr[0], wr[1], h0, g0);
    split_pack(wr[8], wr[9], h1, g1);
    g_bfrag[sl] = make_uint4(h0, h1, g0, g1);

    if (sl < E) {
        const float4* r = (const float4*)(w + sl * C);
        float s = 0.f;
        #pragma unroll
        for (int q = 0; q < 16; ++q) {
            const float4 f = r[q];
            s = fmaf(f.x, f.x, s); s = fmaf(f.y, f.y, s);
            s = fmaf(f.z, f.z, s); s = fmaf(f.w, f.w, s);
        }
        g_wsq[sl] = s;
    }
}

// ===========================================================================
__global__ void __launch_bounds__(128, 5) vq_hmma_kernel(
    const float* __restrict__ x, const float* __restrict__ w,
    float* __restrict__ out_q, float* __restrict__ out_idx,
    float* __restrict__ out_loss, float inv_n)
{
    extern __shared__ float smem[];
    float* xs   = smem + OFF_XS;
    uint4* bbuf = (uint4*)(smem + OFF_B);
    float* wsqs = smem + OFF_WSQ;
    int*   idxb = (int*)(smem + OFF_IDX);
    float* redb = smem + OFF_RED;
    __shared__ int is_last;

    const int tid = threadIdx.x;
    const int l   = tid & 31;
    const int wid = tid >> 5;           // 0..3
    const int wp  = wid * 32;           // warp's first position (local)

    const int p0 = blockIdx.x * 128;
    const int b  = p0 >> 15;
    const int s0 = p0 & (S - 1);
    const float* xb = x + (size_t)b * C * S + s0;

    // ---- x tile -> smem [pos][ch], coalesced, conflict-free ----
    #pragma unroll 8
    for (int it = 0; it < 64; ++it) {
        const int e  = it * 128 + tid;
        const int k  = e >> 7;
        const int pl = e & 127;
        xs[pl * 65 + k] = xb[(size_t)k * S + pl];
    }
    #pragma unroll
    for (int q = 0; q < 4; ++q)
        wsqs[q * 128 + tid] = g_wsq[q * 128 + tid];
    __syncthreads();

    // ---- A fragments (fp16 hi/lo): 2 M-tiles, 4 ksteps x 4 regs each ----
    uint32_t Ahi0[4][4], Alo0[4][4], Ahi1[4][4], Alo1[4][4];
    {
        const int r0 = wp + (l >> 2);
        #pragma unroll
        for (int ks = 0; ks < 4; ++ks) {
            const int k0 = ks * 16 + ((l & 3) << 1);
            split_pack(xs[r0 * 65 + k0],            xs[r0 * 65 + k0 + 1],        Ahi0[ks][0], Alo0[ks][0]);
            split_pack(xs[(r0 + 8) * 65 + k0],      xs[(r0 + 8) * 65 + k0 + 1],  Ahi0[ks][1], Alo0[ks][1]);
            split_pack(xs[r0 * 65 + k0 + 8],        xs[r0 * 65 + k0 + 9],        Ahi0[ks][2], Alo0[ks][2]);
            split_pack(xs[(r0 + 8) * 65 + k0 + 8],  xs[(r0 + 8) * 65 + k0 + 9],  Ahi0[ks][3], Alo0[ks][3]);
            split_pack(xs[(r0 + 16) * 65 + k0],     xs[(r0 + 16) * 65 + k0 + 1], Ahi1[ks][0], Alo1[ks][0]);
            split_pack(xs[(r0 + 24) * 65 + k0],     xs[(r0 + 24) * 65 + k0 + 1], Ahi1[ks][1], Alo1[ks][1]);
            split_pack(xs[(r0 + 16) * 65 + k0 + 8], xs[(r0 + 16) * 65 + k0 + 9], Ahi1[ks][2], Alo1[ks][2]);
            split_pack(xs[(r0 + 24) * 65 + k0 + 8], xs[(r0 + 24) * 65 + k0 + 9], Ahi1[ks][3], Alo1[ks][3]);
        }
    }

    float bv0 = 3.4e38f, bv1 = 3.4e38f, bv2 = 3.4e38f, bv3 = 3.4e38f;
    int   bj0 = 0,       bj1 = 0,       bj2 = 0,       bj3 = 0;

    // ---- 16 chunks of 32 codes ----
    #pragma unroll 1
    for (int chunk = 0; chunk < 16; ++chunk) {
        const int base = chunk * 32;
        __syncthreads();   // previous chunk's readers done

        // fill B: raw copy from precomputed fragment buffer (L2-resident)
        {
            const uint4* src = g_bfrag + chunk * 512;
            #pragma unroll
            for (int it = 0; it < 4; ++it)
                bbuf[it * 128 + tid] = src[it * 128 + tid];
        }
        __syncthreads();

        #pragma unroll 1
        for (int nt = 0; nt < 4; ++nt) {
            float a0[4] = {0.f, 0.f, 0.f, 0.f};   // M-tile 0 (chained)
            float a1[4] = {0.f, 0.f, 0.f, 0.f};   // M-tile 1 (chained)
            #pragma unroll
            for (int ks = 0; ks < 4; ++ks) {
                const uint4 bq = bbuf[(nt * 4 + ks) * 32 + l];
                MMA_F16(a0, Ahi0[ks], bq.x, bq.y);   // hi*hi
                MMA_F16(a1, Ahi1[ks], bq.x, bq.y);
                MMA_F16(a0, Ahi0[ks], bq.z, bq.w);   // hi*lo
                MMA_F16(a1, Ahi1[ks], bq.z, bq.w);
                MMA_F16(a0, Alo0[ks], bq.x, bq.y);   // lo*hi
                MMA_F16(a1, Alo1[ks], bq.x, bq.y);
            }
            const int cb = base + nt * 8 + ((l & 3) << 1);
            const float wq0 = wsqs[cb], wq1 = wsqs[cb + 1];
            // M-tile 0: rows l/4, l/4+8
            {
                const float sc0 = fmaf(-2.f, a0[0], wq0);
                const float sc1 = fmaf(-2.f, a0[1], wq1);
                const float sc2 = fmaf(-2.f, a0[2], wq0);
                const float sc3 = fmaf(-2.f, a0[3], wq1);
                int   jm = (sc1 < sc0) ? cb + 1 : cb;     // tie -> lower j
                float sm = fminf(sc0, sc1);
                bj0 = (sm < bv0) ? jm : bj0;  bv0 = fminf(bv0, sm);
                jm = (sc3 < sc2) ? cb + 1 : cb;
                sm = fminf(sc2, sc3);
                bj1 = (sm < bv1) ? jm : bj1;  bv1 = fminf(bv1, sm);
            }
            // M-tile 1: rows l/4+16, l/4+24
            {
                const float sc0 = fmaf(-2.f, a1[0], wq0);
                const float sc1 = fmaf(-2.f, a1[1], wq1);
                const float sc2 = fmaf(-2.f, a1[2], wq0);
                const float sc3 = fmaf(-2.f, a1[3], wq1);
                int   jm = (sc1 < sc0) ? cb + 1 : cb;
                float sm = fminf(sc0, sc1);
                bj2 = (sm < bv2) ? jm : bj2;  bv2 = fminf(bv2, sm);
                jm = (sc3 < sc2) ? cb + 1 : cb;
                sm = fminf(sc2, sc3);
                bj3 = (sm < bv3) ? jm : bj3;  bv3 = fminf(bv3, sm);
            }
        }
    }

    // ---- cross-lane argmin over quads (cols split across l%4) ----
    #pragma unroll
    for (int off = 1; off <= 2; off <<= 1) {
        float ov; int oj;
        ov = __shfl_xor_sync(0xffffffffu, bv0, off);
        oj = __shfl_xor_sync(0xffffffffu, bj0, off);
        if (ov < bv0 || (ov == bv0 && oj < bj0)) { bv0 = ov; bj0 = oj; }
        ov = __shfl_xor_sync(0xffffffffu, bv1, off);
        oj = __shfl_xor_sync(0xffffffffu, bj1, off);
        if (ov < bv1 || (ov == bv1 && oj < bj1)) { bv1 = ov; bj1 = oj; }
        ov = __shfl_xor_sync(0xffffffffu, bv2, off);
        oj = __shfl_xor_sync(0xffffffffu, bj2, off);
        if (ov < bv2 || (ov == bv2 && oj < bj2)) { bv2 = ov; bj2 = oj; }
        ov = __shfl_xor_sync(0xffffffffu, bv3, off);
        oj = __shfl_xor_sync(0xffffffffu, bj3, off);
        if (ov < bv3 || (ov == bv3 && oj < bj3)) { bv3 = ov; bj3 = oj; }
    }
    if ((l & 3) == 0) {
        const int r = l >> 2;
        idxb[wp + r]      = bj0;
        idxb[wp + r + 8]  = bj1;
        idxb[wp + r + 16] = bj2;
        idxb[wp + r + 24] = bj3;
    }
    __syncthreads();

    // ---- epilogue: 1 thread per position, 64 channels ----
    const int pos = tid;
    const int j   = idxb[pos];
    out_idx[p0 + pos] = (float)j;

    float acc = 0.f;
    const float4* wr = (const float4*)(w + j * C);
    float* qb = out_q + (size_t)b * C * S + s0 + pos;
    #pragma unroll 4
    for (int q4 = 0; q4 < 16; ++q4) {
        const float4 f = wr[q4];
        const float qv[4] = {f.x, f.y, f.z, f.w};
        #pragma unroll
        for (int u = 0; u < 4; ++u) {
            const int c = q4 * 4 + u;
            const float xv = xs[pos * 65 + c];
            const float d = qv[u] - xv;
            qb[(size_t)c * S] = d + xv;    // fl(fl(w-x)+x)
            acc = fmaf(d, d, acc);
        }
    }

    redb[tid] = acc;
    __syncthreads();
    #pragma unroll
    for (int off = 64; off > 0; off >>= 1) {
        if (tid < off) redb[tid] += redb[tid + off];
        __syncthreads();
    }

    // ---- fused deterministic loss finalization (last block) ----
    if (tid == 0) {
        g_partials[blockIdx.x] = redb[0];
        __threadfence();
        const unsigned t = atomicAdd(&g_count, 1u);
        is_last = (t == (unsigned)(gridDim.x - 1)) ? 1 : 0;
    }
    __syncthreads();
    if (is_last) {
        __threadfence();   // acquire: all partials visible
        float a = 0.f;
        #pragma unroll
        for (int q = 0; q < 8; ++q) a += g_partials[q * 128 + tid];
        redb[tid] = a;
        __syncthreads();
        #pragma unroll
        for (int off = 64; off > 0; off >>= 1) {
            if (tid < off) redb[tid] += redb[tid + off];
            __syncthreads();
        }
        if (tid == 0) {
            out_loss[0] = 0.25f * redb[0] * inv_n;
            g_count = 0;   // reset for next graph replay
        }
    }
}

// ---------------------------------------------------------------------------
extern "C" void kernel_launch(void* const* d_in, const int* in_sizes, int n_in,
                              void* d_out, int out_size)
{
    const float* x = (const float*)d_in[0];
    const float* w = (const float*)d_in[1];
    float* out = (float*)d_out;

    const int n_x  = in_sizes[0];   // 8388608
    const int npos = n_x / C;       // 131072

    float* out_q    = out;
    float* out_idx  = out + n_x;
    float* out_loss = out + n_x + npos;

    const int smem_bytes = SMEM_FLOATS * (int)sizeof(float);  // 44544
    cudaFuncSetAttribute(vq_hmma_kernel,
                         cudaFuncAttributeMaxDynamicSharedMemorySize, smem_bytes);

    prep_kernel<<<64, 128>>>(w);
    const int blocks = npos / 128;   // 1024
    vq_hmma_kernel<<<blocks, 128, smem_bytes>>>(x, w, out_q, out_idx,
                                                out_loss, 1.0f / (float)n_x);
}